// round 5
// baseline (speedup 1.0000x reference)
#include <cuda_runtime.h>

// ContrastivePredictionLoss — fused single kernel, R5:
// Streaming loop restructured for explicit MLP: each thread front-batches
// 12 independent LDG.128 (3 tensors x 4 vectors) into register arrays, then
// computes. No register cap — MLP_eff from register allocation is what sets
// streaming bandwidth (R4 showed occupancy alone does not).

#define NB 64
#define ELEMS_PER_BATCH (4 * 256 * 256)      // 262144
#define BLOCKS_PER_BATCH 64
#define NBLOCKS (NB * BLOCKS_PER_BATCH)      // 4096
#define THREADS_A 256
#define ELEMS_PER_BLOCK (ELEMS_PER_BATCH / BLOCKS_PER_BATCH)   // 4096
#define VECS_PER_BLOCK (ELEMS_PER_BLOCK / 4)                   // 1024 float4
#define VECS_PER_THREAD (VECS_PER_BLOCK / THREADS_A)           // 4

// Scratch (allocation-free __device__ globals).
__device__ float g_part_err[NBLOCKS];
__device__ float g_part_unc[NBLOCKS];
__device__ unsigned int g_ticket = 0;   // reset to 0 by the last block each call

__global__ __launch_bounds__(THREADS_A)
void cpl_fused_kernel(const float4* __restrict__ pm,
                      const float4* __restrict__ ps,
                      const float4* __restrict__ tg,
                      float* __restrict__ out) {
    const int blk = blockIdx.x;                      // b * 64 + chunk
    const int tid = threadIdx.x;
    const long base = (long)blk * VECS_PER_BLOCK + tid;

    // ---- front-batched loads: 12 independent LDG.128 ----
    float4 m[VECS_PER_THREAD], t[VECS_PER_THREAD], s[VECS_PER_THREAD];
    #pragma unroll
    for (int i = 0; i < VECS_PER_THREAD; i++) m[i] = pm[base + (long)i * THREADS_A];
    #pragma unroll
    for (int i = 0; i < VECS_PER_THREAD; i++) t[i] = tg[base + (long)i * THREADS_A];
    #pragma unroll
    for (int i = 0; i < VECS_PER_THREAD; i++) s[i] = ps[base + (long)i * THREADS_A];

    float se = 0.0f;   // sum |pm - tg|
    float su = 0.0f;   // sum ps
    #pragma unroll
    for (int i = 0; i < VECS_PER_THREAD; i++) {
        se += fabsf(m[i].x - t[i].x) + fabsf(m[i].y - t[i].y)
            + fabsf(m[i].z - t[i].z) + fabsf(m[i].w - t[i].w);
        su += s[i].x + s[i].y + s[i].z + s[i].w;
    }

    // ---- warp reduce (deterministic shuffle tree) ----
    #pragma unroll
    for (int off = 16; off > 0; off >>= 1) {
        se += __shfl_down_sync(0xFFFFFFFFu, se, off);
        su += __shfl_down_sync(0xFFFFFFFFu, su, off);
    }

    __shared__ float s_se[THREADS_A / 32];
    __shared__ float s_su[THREADS_A / 32];
    const int wid = tid >> 5;
    const int lid = tid & 31;
    if (lid == 0) { s_se[wid] = se; s_su[wid] = su; }
    __syncthreads();

    if (wid == 0) {
        se = (lid < THREADS_A / 32) ? s_se[lid] : 0.0f;
        su = (lid < THREADS_A / 32) ? s_su[lid] : 0.0f;
        #pragma unroll
        for (int off = 4; off > 0; off >>= 1) {
            se += __shfl_down_sync(0xFFFFFFFFu, se, off);
            su += __shfl_down_sync(0xFFFFFFFFu, su, off);
        }
        if (lid == 0) {
            g_part_err[blk] = se;
            g_part_unc[blk] = su;
        }
    }

    // ---- last-block-finalizes handshake ----
    __shared__ bool is_last;
    if (tid == 0) {
        __threadfence();                       // publish this block's partials
        unsigned int tk = atomicAdd(&g_ticket, 1u);
        is_last = (tk == NBLOCKS - 1);
        if (is_last) g_ticket = 0;             // reset for next graph replay
    }
    __syncthreads();
    if (!is_last) return;
    __threadfence();                           // acquire all partials

    // ---- finalize (one block) ----
    // 256 threads = 64 batches x 4 chunks; each thread sums 16 partials.
    __shared__ float s_pe[4][NB];
    __shared__ float s_pu[4][NB];
    {
        const int b = tid & 63;
        const int q = tid >> 6;                // 0..3
        float pe = 0.0f, pu = 0.0f;
        #pragma unroll
        for (int c = 0; c < BLOCKS_PER_BATCH / 4; c++) {
            const int idx = b * BLOCKS_PER_BATCH + q * (BLOCKS_PER_BATCH / 4) + c;
            pe += __ldcg(&g_part_err[idx]);    // written by other SMs: L2 scope
            pu += __ldcg(&g_part_unc[idx]);
        }
        s_pe[q][b] = pe;
        s_pu[q][b] = pu;
    }
    __syncthreads();

    __shared__ float errs[NB];
    __shared__ float uncs[NB];
    if (tid < NB) {
        const float inv = 1.0f / (float)ELEMS_PER_BATCH;
        errs[tid] = (s_pe[0][tid] + s_pe[1][tid] + s_pe[2][tid] + s_pe[3][tid]) * inv;
        uncs[tid] = (s_pu[0][tid] + s_pu[1][tid] + s_pu[2][tid] + s_pu[3][tid]) * inv;
    }
    __syncthreads();

    // Pairwise hinge over upper triangle (i < j), fixed iteration order.
    float acc = 0.0f;
    for (int p = tid; p < NB * NB; p += THREADS_A) {
        const int i = p >> 6;
        const int j = p & 63;
        if (i < j) {
            const float d = ((errs[i] > errs[j]) ? (uncs[j] - uncs[i])
                                                 : (uncs[i] - uncs[j])) + 1.0f;
            acc += fmaxf(d, 0.0f);
        }
    }

    #pragma unroll
    for (int off = 16; off > 0; off >>= 1)
        acc += __shfl_down_sync(0xFFFFFFFFu, acc, off);

    __shared__ float s_acc[THREADS_A / 32];
    if (lid == 0) s_acc[wid] = acc;
    __syncthreads();

    if (tid == 0) {
        float total = 0.0f;
        #pragma unroll
        for (int w = 0; w < THREADS_A / 32; w++) total += s_acc[w];
        const int num_pairs = NB * (NB - 1) / 2;   // 2016
        out[0] = total / (float)num_pairs;
    }
}

extern "C" void kernel_launch(void* const* d_in, const int* in_sizes, int n_in,
                              void* d_out, int out_size) {
    const float4* pm = (const float4*)d_in[0];   // pred_mean
    const float4* ps = (const float4*)d_in[1];   // pred_std
    const float4* tg = (const float4*)d_in[2];   // targets
    float* out = (float*)d_out;

    cpl_fused_kernel<<<NBLOCKS, THREADS_A>>>(pm, ps, tg, out);
}

// round 6
// speedup vs baseline: 1.1638x; 1.1638x over previous
#include <cuda_runtime.h>

// ContrastivePredictionLoss — two-kernel version, R6.
// Stage A: R1's reduce kernel verbatim (measured ~6.2 TB/s; fused variants with
//          an end-of-block atomic ticket all degraded to ~5.0 TB/s — abandoned).
// Stage B: finalize with cooperative float4 loads of the 2048 partials
//          (R1's finalize serialized 32 scalar loads per thread -> 9.7us).

#define NB 64
#define ELEMS_PER_BATCH (4 * 256 * 256)      // 262144
#define BLOCKS_PER_BATCH 32
#define NBLOCKS (NB * BLOCKS_PER_BATCH)      // 2048
#define THREADS_A 256
#define ELEMS_PER_BLOCK (ELEMS_PER_BATCH / BLOCKS_PER_BATCH)   // 8192
#define VECS_PER_BLOCK (ELEMS_PER_BLOCK / 4)                   // 2048 float4
#define VECS_PER_THREAD (VECS_PER_BLOCK / THREADS_A)           // 8

// Scratch (allocation-free __device__ globals).
__device__ float g_part_err[NBLOCKS];
__device__ float g_part_unc[NBLOCKS];

__global__ __launch_bounds__(THREADS_A)
void cpl_reduce_kernel(const float4* __restrict__ pm,
                       const float4* __restrict__ ps,
                       const float4* __restrict__ tg) {
    const int blk = blockIdx.x;                      // b * 32 + chunk
    const int tid = threadIdx.x;
    const long base = (long)blk * VECS_PER_BLOCK;

    float se = 0.0f;   // sum |pm - tg|
    float su = 0.0f;   // sum ps

    #pragma unroll
    for (int i = 0; i < VECS_PER_THREAD; i++) {
        const long idx = base + (long)i * THREADS_A + tid;
        float4 m = pm[idx];
        float4 t = tg[idx];
        float4 s = ps[idx];
        se += fabsf(m.x - t.x) + fabsf(m.y - t.y)
            + fabsf(m.z - t.z) + fabsf(m.w - t.w);
        su += s.x + s.y + s.z + s.w;
    }

    // Warp reduce (deterministic shuffle tree)
    #pragma unroll
    for (int off = 16; off > 0; off >>= 1) {
        se += __shfl_down_sync(0xFFFFFFFFu, se, off);
        su += __shfl_down_sync(0xFFFFFFFFu, su, off);
    }

    __shared__ float s_se[THREADS_A / 32];
    __shared__ float s_su[THREADS_A / 32];
    const int wid = tid >> 5;
    const int lid = tid & 31;
    if (lid == 0) { s_se[wid] = se; s_su[wid] = su; }
    __syncthreads();

    if (wid == 0) {
        se = (lid < THREADS_A / 32) ? s_se[lid] : 0.0f;
        su = (lid < THREADS_A / 32) ? s_su[lid] : 0.0f;
        #pragma unroll
        for (int off = 4; off > 0; off >>= 1) {
            se += __shfl_down_sync(0xFFFFFFFFu, se, off);
            su += __shfl_down_sync(0xFFFFFFFFu, su, off);
        }
        if (lid == 0) {
            g_part_err[blk] = se;
            g_part_unc[blk] = su;
        }
    }
}

#define THREADS_B 256

__global__ __launch_bounds__(THREADS_B)
void cpl_finalize_kernel(float* __restrict__ out) {
    const int tid = threadIdx.x;
    const int wid = tid >> 5;
    const int lid = tid & 31;

    // Cooperative vectorized load of partials:
    // 2048 floats per array = 512 float4. Thread tid -> batch b = tid>>2,
    // quarter q = tid&3. Each (b,q) loads 2 float4 = 8 consecutive partials
    // (batch b's 32 partials are float4 indices [b*8, b*8+8)).
    const int b = tid >> 2;
    const int q = tid & 3;
    const float4* pe4 = (const float4*)g_part_err;
    const float4* pu4 = (const float4*)g_part_unc;

    float4 e0 = pe4[b * 8 + q * 2 + 0];
    float4 e1 = pe4[b * 8 + q * 2 + 1];
    float4 u0 = pu4[b * 8 + q * 2 + 0];
    float4 u1 = pu4[b * 8 + q * 2 + 1];

    float pe = (e0.x + e0.y) + (e0.z + e0.w) + (e1.x + e1.y) + (e1.z + e1.w);
    float pu = (u0.x + u0.y) + (u0.z + u0.w) + (u1.x + u1.y) + (u1.z + u1.w);

    __shared__ float s_pe[4][NB];
    __shared__ float s_pu[4][NB];
    s_pe[q][b] = pe;
    s_pu[q][b] = pu;
    __syncthreads();

    __shared__ float errs[NB];
    __shared__ float uncs[NB];
    if (tid < NB) {
        const float inv = 1.0f / (float)ELEMS_PER_BATCH;
        errs[tid] = ((s_pe[0][tid] + s_pe[1][tid]) + (s_pe[2][tid] + s_pe[3][tid])) * inv;
        uncs[tid] = ((s_pu[0][tid] + s_pu[1][tid]) + (s_pu[2][tid] + s_pu[3][tid])) * inv;
    }
    __syncthreads();

    // Pairwise hinge over upper triangle (i < j), fixed iteration order.
    float acc = 0.0f;
    #pragma unroll
    for (int p = tid; p < NB * NB; p += THREADS_B) {
        const int i = p >> 6;
        const int j = p & 63;
        if (i < j) {
            const float d = ((errs[i] > errs[j]) ? (uncs[j] - uncs[i])
                                                 : (uncs[i] - uncs[j])) + 1.0f;
            acc += fmaxf(d, 0.0f);
        }
    }

    #pragma unroll
    for (int off = 16; off > 0; off >>= 1)
        acc += __shfl_down_sync(0xFFFFFFFFu, acc, off);

    __shared__ float s_acc[THREADS_B / 32];
    if (lid == 0) s_acc[wid] = acc;
    __syncthreads();

    if (tid == 0) {
        float total = 0.0f;
        #pragma unroll
        for (int w = 0; w < THREADS_B / 32; w++) total += s_acc[w];
        const int num_pairs = NB * (NB - 1) / 2;   // 2016
        out[0] = total / (float)num_pairs;
    }
}

extern "C" void kernel_launch(void* const* d_in, const int* in_sizes, int n_in,
                              void* d_out, int out_size) {
    const float4* pm = (const float4*)d_in[0];   // pred_mean
    const float4* ps = (const float4*)d_in[1];   // pred_std
    const float4* tg = (const float4*)d_in[2];   // targets
    float* out = (float*)d_out;

    cpl_reduce_kernel<<<NBLOCKS, THREADS_A>>>(pm, ps, tg);
    cpl_finalize_kernel<<<1, THREADS_B>>>(out);
}